// round 16
// baseline (speedup 1.0000x reference)
#include <cuda_runtime.h>
#include <cstdint>
#include <cfloat>

#define NN 50000        // nodes
#define NE 800000       // edges
#define NG 64           // graphs
#define DD 96           // dim
#define NL 4            // GIN layers
#define NH 5            // heads
#define BN_EPS 1e-5f
#define SCAN_BLK 196    // ceil(50000/256)

// ---------------- scratch (static device globals; no allocs allowed) ----------
__device__ __align__(256) float g_h  [NN * DD];
__device__ __align__(256) float g_agg[NN * DD];   // z buffer (h+agg), then z2
__device__ __align__(256) float g_y  [NN * DD];
__device__ __align__(256) float g_stats[NL * 2 * 2 * DD];
__device__ __align__(256) unsigned g_pool[NH * NG * DD];
// CSR scratch
__device__ __align__(256) int g_cnt [NN];
__device__ __align__(256) int g_off [NN + 1];
__device__ __align__(256) int g_eidx[NE];
__device__ __align__(256) int g_bsum[256];

// ---------------- init ---------------------------------------------------------
__global__ void init_kernel() {
    int idx = blockIdx.x * blockDim.x + threadIdx.x;
    int stride = gridDim.x * blockDim.x;
    for (int i = idx; i < NL * 2 * 2 * DD; i += stride) g_stats[i] = 0.f;
    for (int i = idx; i < NH * NG * DD; i += stride) g_pool[i] = 0u;
    for (int i = idx; i < NN; i += stride) g_cnt[i] = 0;
}

// ---------------- CSR build ----------------------------------------------------
__global__ void csr_count_kernel(const int* __restrict__ dst) {
    int e = blockIdx.x * blockDim.x + threadIdx.x;
    if (e < NE) atomicAdd(&g_cnt[dst[e]], 1);
}

__global__ void scanA_kernel() {
    __shared__ int s[256];
    int t = threadIdx.x;
    int idx = blockIdx.x * 256 + t;
    int c = (idx < NN) ? g_cnt[idx] : 0;
    s[t] = c; __syncthreads();
    #pragma unroll
    for (int o = 128; o > 0; o >>= 1) {
        if (t < o) s[t] += s[t + o];
        __syncthreads();
    }
    if (t == 0) g_bsum[blockIdx.x] = s[0];
}

__global__ void scanB_kernel() {
    __shared__ int s[256];
    int t = threadIdx.x;
    int v = (t < SCAN_BLK) ? g_bsum[t] : 0;
    s[t] = v; __syncthreads();
    #pragma unroll
    for (int o = 1; o < 256; o <<= 1) {
        int x = (t >= o) ? s[t - o] : 0;
        __syncthreads();
        s[t] += x;
        __syncthreads();
    }
    g_bsum[t] = s[t] - v;   // exclusive
}

__global__ void scanC_kernel() {
    __shared__ int s[256];
    int t = threadIdx.x;
    int idx = blockIdx.x * 256 + t;
    int c = (idx < NN) ? g_cnt[idx] : 0;
    s[t] = c; __syncthreads();
    #pragma unroll
    for (int o = 1; o < 256; o <<= 1) {
        int x = (t >= o) ? s[t - o] : 0;
        __syncthreads();
        s[t] += x;
        __syncthreads();
    }
    int excl = g_bsum[blockIdx.x] + s[t] - c;
    if (idx < NN) { g_off[idx] = excl; g_cnt[idx] = 0; }
    if (idx == NN - 1) g_off[NN] = excl + c;
}

__global__ void csr_fill_kernel(const int* __restrict__ src,
                                const int* __restrict__ dst) {
    int e = blockIdx.x * blockDim.x + threadIdx.x;
    if (e >= NE) return;
    int d = dst[e];
    int pos = g_off[d] + atomicAdd(&g_cnt[d], 1);
    g_eidx[pos] = src[e];
}

// ------ gather aggregation: warp-per-node, unroll-2 (measured-good) ------------
__global__ __launch_bounds__(256) void agg_kernel(const float4* __restrict__ h4,
                                                  float4* __restrict__ z4) {
    int gtid = blockIdx.x * 256 + threadIdx.x;
    int node = gtid >> 5;
    int lane = threadIdx.x & 31;
    if (node >= NN || lane >= 24) return;
    int o0 = g_off[node], o1 = g_off[node + 1];
    float4 a0 = __ldg(&h4[node * 24 + lane]);
    float4 a1 = make_float4(0.f, 0.f, 0.f, 0.f);
    int j = o0;
    for (; j + 1 < o1; j += 2) {
        int s0 = __ldg(&g_eidx[j]);
        int s1 = __ldg(&g_eidx[j + 1]);
        float4 v0 = __ldg(&h4[s0 * 24 + lane]);
        float4 v1 = __ldg(&h4[s1 * 24 + lane]);
        a0.x += v0.x; a0.y += v0.y; a0.z += v0.z; a0.w += v0.w;
        a1.x += v1.x; a1.y += v1.y; a1.z += v1.z; a1.w += v1.w;
    }
    if (j < o1) {
        int s0 = __ldg(&g_eidx[j]);
        float4 v0 = __ldg(&h4[s0 * 24 + lane]);
        a0.x += v0.x; a0.y += v0.y; a0.z += v0.z; a0.w += v0.w;
    }
    a0.x += a1.x; a0.y += a1.y; a0.z += a1.z; a0.w += a1.w;
    z4[node * 24 + lane] = a0;
}

// ---------------- packed f32x2 helpers -----------------------------------------
__device__ __forceinline__ unsigned long long pk2(float x) {
    unsigned long long r;
    asm("mov.b64 %0, {%1, %1};" : "=l"(r) : "f"(x));
    return r;
}
__device__ __forceinline__ void fma2(unsigned long long& d,
                                     unsigned long long a, unsigned long long b) {
    asm("fma.rn.f32x2 %0, %1, %2, %0;" : "+l"(d) : "l"(a), "l"(b));
}
__device__ __forceinline__ void unpk2(unsigned long long v, float& lo, float& hi) {
    asm("mov.b64 {%0, %1}, %2;" : "=f"(lo), "=f"(hi) : "l"(v));
}

// ---------------- fused GEMM: TR=96, 256 threads, 3 blocks/SM (measured-good) ---
// MODE 0: z = A             MODE 1: z = relu(bn(A)), aff in-block from stats_in
template<int MODE>
__global__ __launch_bounds__(256) void gemm_kernel(
    const float* __restrict__ A,
    const float* __restrict__ W, const float* __restrict__ bias,
    const float* __restrict__ stats_in,
    const float* __restrict__ gamma, const float* __restrict__ beta,
    float* __restrict__ out, float* __restrict__ stats_out)
{
    constexpr int TR = 96;
    constexpr int SROW = 100;
    extern __shared__ float sm[];
    float* zs   = sm;                  // TR * SROW = 9600
    float* ws   = sm + TR * SROW;      // 96*96 = 9216
    float* saff = ws + DD * DD;        // 96
    float* taff = saff + DD;           // 96

    const int tid = threadIdx.x;
    const int tx = tid & 15;
    const int ty = tid >> 4;
    const int row0 = blockIdx.x * TR;

    if (MODE == 1) {
        if (tid < DD) {
            const float inv_n = 1.f / (float)NN;
            float mean = stats_in[tid] * inv_n;
            float var  = stats_in[DD + tid] * inv_n - mean * mean;
            float s = gamma[tid] * rsqrtf(var + BN_EPS);
            saff[tid] = s;
            taff[tid] = beta[tid] - mean * s;
        }
        __syncthreads();
    }

    {
        float4* ws4 = reinterpret_cast<float4*>(ws);
        const float4* W4 = reinterpret_cast<const float4*>(W);
        #pragma unroll
        for (int i = 0; i < (DD * DD / 4) / 256; i++)
            ws4[tid + i * 256] = W4[tid + i * 256];
    }
    #pragma unroll
    for (int t = 0; t < (TR * (DD / 4)) / 256; t++) {
        int i = tid + t * 256;
        int r = i / (DD / 4), c4 = i - r * (DD / 4);
        int grow = row0 + r;
        float4 v;
        if (grow < NN) {
            v = reinterpret_cast<const float4*>(A)[grow * (DD / 4) + c4];
            if (MODE == 1) {
                int k = c4 * 4;
                v.x = fmaxf(saff[k + 0] * v.x + taff[k + 0], 0.f);
                v.y = fmaxf(saff[k + 1] * v.y + taff[k + 1], 0.f);
                v.z = fmaxf(saff[k + 2] * v.z + taff[k + 2], 0.f);
                v.w = fmaxf(saff[k + 3] * v.w + taff[k + 3], 0.f);
            }
        } else {
            v = make_float4(0.f, 0.f, 0.f, 0.f);
        }
        *reinterpret_cast<float4*>(zs + r * SROW + c4 * 4) = v;
    }
    __syncthreads();

    unsigned long long acc[6][3];
    #pragma unroll
    for (int i = 0; i < 6; i++)
        #pragma unroll
        for (int j = 0; j < 3; j++) acc[i][j] = 0ull;

    const int cbase = 2 * tx;
    #pragma unroll 8
    for (int k = 0; k < DD; k++) {
        unsigned long long a2[6], w2[3];
        #pragma unroll
        for (int i = 0; i < 6; i++) a2[i] = pk2(zs[(16 * i + ty) * SROW + k]);
        #pragma unroll
        for (int j = 0; j < 3; j++)
            w2[j] = *reinterpret_cast<const unsigned long long*>(ws + k * DD + cbase + 32 * j);
        #pragma unroll
        for (int i = 0; i < 6; i++)
            #pragma unroll
            for (int j = 0; j < 3; j++) fma2(acc[i][j], a2[i], w2[j]);
    }

    float blo[3], bhi[3];
    #pragma unroll
    for (int j = 0; j < 3; j++) {
        blo[j] = __ldg(&bias[cbase + 32 * j]);
        bhi[j] = __ldg(&bias[cbase + 32 * j + 1]);
    }
    float cs[6], cq[6];
    #pragma unroll
    for (int j = 0; j < 6; j++) { cs[j] = 0.f; cq[j] = 0.f; }

    #pragma unroll
    for (int i = 0; i < 6; i++) {
        int grow = row0 + 16 * i + ty;
        if (grow < NN) {
            #pragma unroll
            for (int j = 0; j < 3; j++) {
                float lo, hi;
                unpk2(acc[i][j], lo, hi);
                lo += blo[j]; hi += bhi[j];
                *reinterpret_cast<float2*>(out + grow * DD + cbase + 32 * j) =
                    make_float2(lo, hi);
                cs[2 * j] += lo;     cq[2 * j] += lo * lo;
                cs[2 * j + 1] += hi; cq[2 * j + 1] += hi * hi;
            }
        }
    }

    __syncthreads();
    float* sred = sm; // [2][16][96]
    #pragma unroll
    for (int j = 0; j < 3; j++) {
        #pragma unroll
        for (int q = 0; q < 2; q++) {
            int c = cbase + 32 * j + q;
            sred[ty * DD + c] = cs[2 * j + q];
            sred[16 * DD + ty * DD + c] = cq[2 * j + q];
        }
    }
    __syncthreads();
    if (tid < DD) {
        float s = 0.f, q = 0.f;
        #pragma unroll
        for (int t = 0; t < 16; t++) {
            s += sred[t * DD + tid];
            q += sred[16 * DD + t * DD + tid];
        }
        atomicAdd(&stats_out[tid], s);
        atomicAdd(&stats_out[DD + tid], q);
    }
}

// ---------------- fused bn + prelu + max-pool: 480 threads ----------------------
__device__ __forceinline__ unsigned f2key(float f) {
    int i = __float_as_int(f);
    return (i >= 0) ? ((unsigned)i ^ 0x80000000u) : ~(unsigned)i;
}
__device__ __forceinline__ float4 fmax4(float4 a, float4 b) {
    return make_float4(fmaxf(a.x, b.x), fmaxf(a.y, b.y),
                       fmaxf(a.z, b.z), fmaxf(a.w, b.w));
}

__global__ __launch_bounds__(480) void prelupool_kernel(
    const float* __restrict__ stats_in,
    const float* __restrict__ gamma, const float* __restrict__ beta,
    const float* __restrict__ prelu_a, int slot)
{
    __shared__ float saff[DD], taff[DD];
    __shared__ float4 smx0[20][24];
    __shared__ float4 smx1[20][24];
    const int tid = threadIdx.x;
    const int c4 = tid % 24;
    const int rgrp = tid / 24;   // 0..19

    if (tid < DD) {
        const float inv_n = 1.f / (float)NN;
        float mean = stats_in[tid] * inv_n;
        float var  = stats_in[DD + tid] * inv_n - mean * mean;
        float s = gamma[tid] * rsqrtf(var + BN_EPS);
        saff[tid] = s;
        taff[tid] = beta[tid] - mean * s;
    }
    __syncthreads();

    const float a = __ldg(prelu_a);
    const float4 sv = *reinterpret_cast<const float4*>(saff + c4 * 4);
    const float4 tv = *reinterpret_cast<const float4*>(taff + c4 * 4);

    const int r0 = blockIdx.x * 64;
    const int rend = min(NN, r0 + 64);
    const int g0 = (int)(((long long)r0 * NG) / NN);
    int b = (int)(((long long)(g0 + 1) * NN + NG - 1) / NG);
    if (b > rend) b = rend;

    float4 m0 = make_float4(-FLT_MAX, -FLT_MAX, -FLT_MAX, -FLT_MAX);
    float4 m1 = m0;

    for (int r = r0 + rgrp; r < rend; r += 20) {
        float4 z = *reinterpret_cast<const float4*>(g_agg + r * DD + c4 * 4);
        float4 v;
        float u;
        u = sv.x * z.x + tv.x; v.x = (u >= 0.f) ? u : a * u;
        u = sv.y * z.y + tv.y; v.y = (u >= 0.f) ? u : a * u;
        u = sv.z * z.z + tv.z; v.z = (u >= 0.f) ? u : a * u;
        u = sv.w * z.w + tv.w; v.w = (u >= 0.f) ? u : a * u;
        *reinterpret_cast<float4*>(g_h + r * DD + c4 * 4) = v;
        if (r < b) m0 = fmax4(m0, v); else m1 = fmax4(m1, v);
    }
    smx0[rgrp][c4] = m0;
    smx1[rgrp][c4] = m1;
    __syncthreads();

    if (rgrp == 0) {
        #pragma unroll
        for (int g = 1; g < 20; g++) {
            m0 = fmax4(m0, smx0[g][c4]);
            m1 = fmax4(m1, smx1[g][c4]);
        }
        unsigned* p0 = &g_pool[slot * NG * DD + g0 * DD + c4 * 4];
        atomicMax(p0 + 0, f2key(m0.x));
        atomicMax(p0 + 1, f2key(m0.y));
        atomicMax(p0 + 2, f2key(m0.z));
        atomicMax(p0 + 3, f2key(m0.w));
        if (b < rend) {
            unsigned* p1 = &g_pool[slot * NG * DD + (g0 + 1) * DD + c4 * 4];
            atomicMax(p1 + 0, f2key(m1.x));
            atomicMax(p1 + 1, f2key(m1.y));
            atomicMax(p1 + 2, f2key(m1.z));
            atomicMax(p1 + 3, f2key(m1.w));
        }
    }
}

// ---------------- per-graph max pool for the input layer -----------------------
__global__ void pool_kernel(const float* __restrict__ h, int slot) {
    int g = blockIdx.x, part = blockIdx.y, d = threadIdx.x;
    int lo_g = (g * NN + (NG - 1)) / NG;
    int hi_g = ((g + 1) * NN + (NG - 1)) / NG;
    int chunk = (hi_g - lo_g + 7) >> 3;
    int lo = lo_g + part * chunk;
    int hi = min(hi_g, lo + chunk);
    float m = -3.402823466e38f;
    for (int r = lo; r < hi; r++) m = fmaxf(m, __ldg(&h[r * DD + d]));
    if (hi > lo) atomicMax(&g_pool[slot * NG * DD + g * DD + d], f2key(m));
}

// ---------------- heads: (NH x 8) grid, 8 graphs per block ----------------------
__global__ void heads_kernel(const float* __restrict__ lin_W,
                             const float* __restrict__ lin_b,
                             float* __restrict__ out)
{
    extern __shared__ float sm[];
    float* ps = sm;             // 8*96
    float* ws = sm + 8 * DD;    // 96*96
    int l = blockIdx.x, part = blockIdx.y, tid = threadIdx.x;
    int gbase = part * 8;

    for (int i = tid; i < 8 * DD; i += DD) {
        unsigned key = g_pool[l * NG * DD + gbase * DD + i];
        int b = (key & 0x80000000u) ? (int)(key ^ 0x80000000u) : (int)(~key);
        ps[i] = __int_as_float(b);
    }
    for (int i = tid; i < DD * DD; i += DD) ws[i] = lin_W[l * DD * DD + i];
    __syncthreads();

    float bv = lin_b[l * DD + tid];
    for (int gg = 0; gg < 8; gg++) {
        float acc = bv;
        #pragma unroll 4
        for (int k = 0; k < DD; k++) acc = fmaf(ps[gg * DD + k], ws[k * DD + tid], acc);
        out[(gbase + gg) * (DD * NH) + tid * NH + l] = acc;
    }
}

// ---------------- host orchestration -------------------------------------------
extern "C" void kernel_launch(void* const* d_in, const int* in_sizes, int n_in,
                              void* d_out, int out_size)
{
    const float* h_in   = (const float*)d_in[0];
    const float* W1     = (const float*)d_in[1];
    const float* b1     = (const float*)d_in[2];
    const float* bn1g   = (const float*)d_in[3];
    const float* bn1b   = (const float*)d_in[4];
    const float* W2     = (const float*)d_in[5];
    const float* b2     = (const float*)d_in[6];
    const float* bng    = (const float*)d_in[7];
    const float* bnb    = (const float*)d_in[8];
    const float* prelua = (const float*)d_in[9];
    const float* linW   = (const float*)d_in[10];
    const float* linb   = (const float*)d_in[11];
    const int*   src    = (const int*)d_in[12];
    const int*   dst    = (const int*)d_in[13];
    float* out = (float*)d_out;

    void* p;
    cudaGetSymbolAddress(&p, g_h);     float* hbuf = (float*)p;
    cudaGetSymbolAddress(&p, g_agg);   float* zbuf = (float*)p;
    cudaGetSymbolAddress(&p, g_y);     float* ybuf = (float*)p;
    cudaGetSymbolAddress(&p, g_stats); float* stats = (float*)p;

    const int gemm_smem  = (96 * 100 + DD * DD + 2 * DD) * (int)sizeof(float);  // 76032
    const int heads_smem = (8 * DD + DD * DD) * (int)sizeof(float);             // 39936
    cudaFuncSetAttribute(gemm_kernel<0>, cudaFuncAttributeMaxDynamicSharedMemorySize, gemm_smem);
    cudaFuncSetAttribute(gemm_kernel<1>, cudaFuncAttributeMaxDynamicSharedMemorySize, gemm_smem);
    cudaFuncSetAttribute(heads_kernel,   cudaFuncAttributeMaxDynamicSharedMemorySize, heads_smem);

    const int gemm_blocks = (NN + 95) / 96;     // 521
    const int edge_blocks = (NE + 255) / 256;
    const int agg_blocks  = (NN * 32 + 255) / 256;
    const int pp_blocks   = (NN + 63) / 64;     // 782

    init_kernel<<<128, 256>>>();
    csr_count_kernel<<<edge_blocks, 256>>>(dst);
    scanA_kernel<<<SCAN_BLK, 256>>>();
    scanB_kernel<<<1, 256>>>();
    scanC_kernel<<<SCAN_BLK, 256>>>();
    csr_fill_kernel<<<edge_blocks, 256>>>(src, dst);

    pool_kernel<<<dim3(NG, 8), DD>>>(h_in, 0);

    for (int l = 0; l < NL; l++) {
        const float* hcur = (l == 0) ? h_in : hbuf;
        float* st1 = stats + (l * 2 + 0) * 2 * DD;
        float* st2 = stats + (l * 2 + 1) * 2 * DD;

        agg_kernel<<<agg_blocks, 256>>>(
            reinterpret_cast<const float4*>(hcur),
            reinterpret_cast<float4*>(zbuf));

        gemm_kernel<0><<<gemm_blocks, 256, gemm_smem>>>(
            zbuf, W1 + l * DD * DD, b1 + l * DD,
            nullptr, nullptr, nullptr, ybuf, st1);

        gemm_kernel<1><<<gemm_blocks, 256, gemm_smem>>>(
            ybuf, W2 + l * DD * DD, b2 + l * DD,
            st1, bn1g + l * DD, bn1b + l * DD, zbuf, st2);

        prelupool_kernel<<<pp_blocks, 480>>>(
            st2, bng + l * DD, bnb + l * DD, prelua, l + 1);
    }

    heads_kernel<<<dim3(NH, 8), DD, heads_smem>>>(linW, linb, out);
}

// round 17
// speedup vs baseline: 1.5233x; 1.5233x over previous
#include <cuda_runtime.h>
#include <cstdint>
#include <cfloat>

#define NN 50000        // nodes
#define NE 800000       // edges
#define NG 64           // graphs
#define DD 96           // dim
#define NL 4            // GIN layers
#define NH 5            // heads
#define BN_EPS 1e-5f
#define SCAN_BLK 196    // ceil(50000/256)

// ---------------- scratch (static device globals; no allocs allowed) ----------
__device__ __align__(256) float g_h  [NN * DD];
__device__ __align__(256) float g_agg[NN * DD];   // z buffer (h+agg), then z2
__device__ __align__(256) float g_y  [NN * DD];
__device__ __align__(256) float g_stats[NL * 2 * 2 * DD];
__device__ __align__(256) unsigned g_pool[NH * NG * DD];
// CSR scratch
__device__ __align__(256) int g_cnt [NN];
__device__ __align__(256) int g_off [NN + 1];
__device__ __align__(256) int g_eidx[NE];
__device__ __align__(256) int g_bsum[256];

// ---------------- init ---------------------------------------------------------
__global__ void init_kernel() {
    int idx = blockIdx.x * blockDim.x + threadIdx.x;
    int stride = gridDim.x * blockDim.x;
    for (int i = idx; i < NL * 2 * 2 * DD; i += stride) g_stats[i] = 0.f;
    for (int i = idx; i < NH * NG * DD; i += stride) g_pool[i] = 0u;
    for (int i = idx; i < NN; i += stride) g_cnt[i] = 0;
}

// ---------------- CSR build ----------------------------------------------------
__global__ void csr_count_kernel(const int* __restrict__ dst) {
    int e = blockIdx.x * blockDim.x + threadIdx.x;
    if (e < NE) atomicAdd(&g_cnt[dst[e]], 1);
}

__global__ void scanA_kernel() {
    __shared__ int s[256];
    int t = threadIdx.x;
    int idx = blockIdx.x * 256 + t;
    int c = (idx < NN) ? g_cnt[idx] : 0;
    s[t] = c; __syncthreads();
    #pragma unroll
    for (int o = 128; o > 0; o >>= 1) {
        if (t < o) s[t] += s[t + o];
        __syncthreads();
    }
    if (t == 0) g_bsum[blockIdx.x] = s[0];
}

__global__ void scanB_kernel() {
    __shared__ int s[256];
    int t = threadIdx.x;
    int v = (t < SCAN_BLK) ? g_bsum[t] : 0;
    s[t] = v; __syncthreads();
    #pragma unroll
    for (int o = 1; o < 256; o <<= 1) {
        int x = (t >= o) ? s[t - o] : 0;
        __syncthreads();
        s[t] += x;
        __syncthreads();
    }
    g_bsum[t] = s[t] - v;   // exclusive
}

__global__ void scanC_kernel() {
    __shared__ int s[256];
    int t = threadIdx.x;
    int idx = blockIdx.x * 256 + t;
    int c = (idx < NN) ? g_cnt[idx] : 0;
    s[t] = c; __syncthreads();
    #pragma unroll
    for (int o = 1; o < 256; o <<= 1) {
        int x = (t >= o) ? s[t - o] : 0;
        __syncthreads();
        s[t] += x;
        __syncthreads();
    }
    int excl = g_bsum[blockIdx.x] + s[t] - c;
    if (idx < NN) { g_off[idx] = excl; g_cnt[idx] = 0; }
    if (idx == NN - 1) g_off[NN] = excl + c;
}

__global__ void csr_fill_kernel(const int* __restrict__ src,
                                const int* __restrict__ dst) {
    int e = blockIdx.x * blockDim.x + threadIdx.x;
    if (e >= NE) return;
    int d = dst[e];
    int pos = g_off[d] + atomicAdd(&g_cnt[d], 1);
    g_eidx[pos] = src[e];
}

// ------ gather aggregation: warp-per-node, unroll-2 (measured-good) ------------
__global__ __launch_bounds__(256) void agg_kernel(const float4* __restrict__ h4,
                                                  float4* __restrict__ z4) {
    int gtid = blockIdx.x * 256 + threadIdx.x;
    int node = gtid >> 5;
    int lane = threadIdx.x & 31;
    if (node >= NN || lane >= 24) return;
    int o0 = g_off[node], o1 = g_off[node + 1];
    float4 a0 = __ldg(&h4[node * 24 + lane]);
    float4 a1 = make_float4(0.f, 0.f, 0.f, 0.f);
    int j = o0;
    for (; j + 1 < o1; j += 2) {
        int s0 = __ldg(&g_eidx[j]);
        int s1 = __ldg(&g_eidx[j + 1]);
        float4 v0 = __ldg(&h4[s0 * 24 + lane]);
        float4 v1 = __ldg(&h4[s1 * 24 + lane]);
        a0.x += v0.x; a0.y += v0.y; a0.z += v0.z; a0.w += v0.w;
        a1.x += v1.x; a1.y += v1.y; a1.z += v1.z; a1.w += v1.w;
    }
    if (j < o1) {
        int s0 = __ldg(&g_eidx[j]);
        float4 v0 = __ldg(&h4[s0 * 24 + lane]);
        a0.x += v0.x; a0.y += v0.y; a0.z += v0.z; a0.w += v0.w;
    }
    a0.x += a1.x; a0.y += a1.y; a0.z += a1.z; a0.w += a1.w;
    z4[node * 24 + lane] = a0;
}

// ---------------- packed f32x2 helpers -----------------------------------------
__device__ __forceinline__ unsigned long long pk2(float x) {
    unsigned long long r;
    asm("mov.b64 %0, {%1, %1};" : "=l"(r) : "f"(x));
    return r;
}
__device__ __forceinline__ void fma2(unsigned long long& d,
                                     unsigned long long a, unsigned long long b) {
    asm("fma.rn.f32x2 %0, %1, %2, %0;" : "+l"(d) : "l"(a), "l"(b));
}
__device__ __forceinline__ void unpk2(unsigned long long v, float& lo, float& hi) {
    asm("mov.b64 {%0, %1}, %2;" : "=f"(lo), "=f"(hi) : "l"(v));
}

// ---------------- fused GEMM: TR=96, 256 threads, 3 blocks/SM (measured-good) ---
// MODE 0: z = A             MODE 1: z = relu(bn(A)), aff in-block from stats_in
template<int MODE>
__global__ __launch_bounds__(256) void gemm_kernel(
    const float* __restrict__ A,
    const float* __restrict__ W, const float* __restrict__ bias,
    const float* __restrict__ stats_in,
    const float* __restrict__ gamma, const float* __restrict__ beta,
    float* __restrict__ out, float* __restrict__ stats_out)
{
    constexpr int TR = 96;
    constexpr int SROW = 100;
    extern __shared__ float sm[];
    float* zs   = sm;                  // TR * SROW = 9600
    float* ws   = sm + TR * SROW;      // 96*96 = 9216
    float* saff = ws + DD * DD;        // 96
    float* taff = saff + DD;           // 96

    const int tid = threadIdx.x;
    const int tx = tid & 15;
    const int ty = tid >> 4;
    const int row0 = blockIdx.x * TR;

    if (MODE == 1) {
        if (tid < DD) {
            const float inv_n = 1.f / (float)NN;
            float mean = stats_in[tid] * inv_n;
            float var  = stats_in[DD + tid] * inv_n - mean * mean;
            float s = gamma[tid] * rsqrtf(var + BN_EPS);
            saff[tid] = s;
            taff[tid] = beta[tid] - mean * s;
        }
        __syncthreads();
    }

    {
        float4* ws4 = reinterpret_cast<float4*>(ws);
        const float4* W4 = reinterpret_cast<const float4*>(W);
        #pragma unroll
        for (int i = 0; i < (DD * DD / 4) / 256; i++)
            ws4[tid + i * 256] = W4[tid + i * 256];
    }
    #pragma unroll
    for (int t = 0; t < (TR * (DD / 4)) / 256; t++) {
        int i = tid + t * 256;
        int r = i / (DD / 4), c4 = i - r * (DD / 4);
        int grow = row0 + r;
        float4 v;
        if (grow < NN) {
            v = reinterpret_cast<const float4*>(A)[grow * (DD / 4) + c4];
            if (MODE == 1) {
                int k = c4 * 4;
                v.x = fmaxf(saff[k + 0] * v.x + taff[k + 0], 0.f);
                v.y = fmaxf(saff[k + 1] * v.y + taff[k + 1], 0.f);
                v.z = fmaxf(saff[k + 2] * v.z + taff[k + 2], 0.f);
                v.w = fmaxf(saff[k + 3] * v.w + taff[k + 3], 0.f);
            }
        } else {
            v = make_float4(0.f, 0.f, 0.f, 0.f);
        }
        *reinterpret_cast<float4*>(zs + r * SROW + c4 * 4) = v;
    }
    __syncthreads();

    unsigned long long acc[6][3];
    #pragma unroll
    for (int i = 0; i < 6; i++)
        #pragma unroll
        for (int j = 0; j < 3; j++) acc[i][j] = 0ull;

    const int cbase = 2 * tx;
    #pragma unroll 8
    for (int k = 0; k < DD; k++) {
        unsigned long long a2[6], w2[3];
        #pragma unroll
        for (int i = 0; i < 6; i++) a2[i] = pk2(zs[(16 * i + ty) * SROW + k]);
        #pragma unroll
        for (int j = 0; j < 3; j++)
            w2[j] = *reinterpret_cast<const unsigned long long*>(ws + k * DD + cbase + 32 * j);
        #pragma unroll
        for (int i = 0; i < 6; i++)
            #pragma unroll
            for (int j = 0; j < 3; j++) fma2(acc[i][j], a2[i], w2[j]);
    }

    float blo[3], bhi[3];
    #pragma unroll
    for (int j = 0; j < 3; j++) {
        blo[j] = __ldg(&bias[cbase + 32 * j]);
        bhi[j] = __ldg(&bias[cbase + 32 * j + 1]);
    }
    float cs[6], cq[6];
    #pragma unroll
    for (int j = 0; j < 6; j++) { cs[j] = 0.f; cq[j] = 0.f; }

    #pragma unroll
    for (int i = 0; i < 6; i++) {
        int grow = row0 + 16 * i + ty;
        if (grow < NN) {
            #pragma unroll
            for (int j = 0; j < 3; j++) {
                float lo, hi;
                unpk2(acc[i][j], lo, hi);
                lo += blo[j]; hi += bhi[j];
                *reinterpret_cast<float2*>(out + grow * DD + cbase + 32 * j) =
                    make_float2(lo, hi);
                cs[2 * j] += lo;     cq[2 * j] += lo * lo;
                cs[2 * j + 1] += hi; cq[2 * j + 1] += hi * hi;
            }
        }
    }

    __syncthreads();
    float* sred = sm; // [2][16][96]
    #pragma unroll
    for (int j = 0; j < 3; j++) {
        #pragma unroll
        for (int q = 0; q < 2; q++) {
            int c = cbase + 32 * j + q;
            sred[ty * DD + c] = cs[2 * j + q];
            sred[16 * DD + ty * DD + c] = cq[2 * j + q];
        }
    }
    __syncthreads();
    if (tid < DD) {
        float s = 0.f, q = 0.f;
        #pragma unroll
        for (int t = 0; t < 16; t++) {
            s += sred[t * DD + tid];
            q += sred[16 * DD + t * DD + tid];
        }
        atomicAdd(&stats_out[tid], s);
        atomicAdd(&stats_out[DD + tid], q);
    }
}

// ---------------- fused bn + prelu + max-pool: 240 threads (measured-good) ------
__device__ __forceinline__ unsigned f2key(float f) {
    int i = __float_as_int(f);
    return (i >= 0) ? ((unsigned)i ^ 0x80000000u) : ~(unsigned)i;
}
__device__ __forceinline__ float4 fmax4(float4 a, float4 b) {
    return make_float4(fmaxf(a.x, b.x), fmaxf(a.y, b.y),
                       fmaxf(a.z, b.z), fmaxf(a.w, b.w));
}

__global__ __launch_bounds__(240) void prelupool_kernel(
    const float* __restrict__ stats_in,
    const float* __restrict__ gamma, const float* __restrict__ beta,
    const float* __restrict__ prelu_a, int slot)
{
    __shared__ float saff[DD], taff[DD];
    __shared__ float4 smx0[10][24];
    __shared__ float4 smx1[10][24];
    const int tid = threadIdx.x;
    const int c4 = tid % 24;
    const int rgrp = tid / 24;

    if (tid < DD) {
        const float inv_n = 1.f / (float)NN;
        float mean = stats_in[tid] * inv_n;
        float var  = stats_in[DD + tid] * inv_n - mean * mean;
        float s = gamma[tid] * rsqrtf(var + BN_EPS);
        saff[tid] = s;
        taff[tid] = beta[tid] - mean * s;
    }
    __syncthreads();

    const float a = __ldg(prelu_a);
    const float4 sv = *reinterpret_cast<const float4*>(saff + c4 * 4);
    const float4 tv = *reinterpret_cast<const float4*>(taff + c4 * 4);

    const int r0 = blockIdx.x * 64;
    const int rend = min(NN, r0 + 64);
    const int g0 = (int)(((long long)r0 * NG) / NN);
    int b = (int)(((long long)(g0 + 1) * NN + NG - 1) / NG);
    if (b > rend) b = rend;

    float4 m0 = make_float4(-FLT_MAX, -FLT_MAX, -FLT_MAX, -FLT_MAX);
    float4 m1 = m0;

    for (int r = r0 + rgrp; r < rend; r += 10) {
        float4 z = *reinterpret_cast<const float4*>(g_agg + r * DD + c4 * 4);
        float4 v;
        float u;
        u = sv.x * z.x + tv.x; v.x = (u >= 0.f) ? u : a * u;
        u = sv.y * z.y + tv.y; v.y = (u >= 0.f) ? u : a * u;
        u = sv.z * z.z + tv.z; v.z = (u >= 0.f) ? u : a * u;
        u = sv.w * z.w + tv.w; v.w = (u >= 0.f) ? u : a * u;
        *reinterpret_cast<float4*>(g_h + r * DD + c4 * 4) = v;
        if (r < b) m0 = fmax4(m0, v); else m1 = fmax4(m1, v);
    }
    smx0[rgrp][c4] = m0;
    smx1[rgrp][c4] = m1;
    __syncthreads();

    if (rgrp == 0) {
        #pragma unroll
        for (int g = 1; g < 10; g++) {
            m0 = fmax4(m0, smx0[g][c4]);
            m1 = fmax4(m1, smx1[g][c4]);
        }
        unsigned* p0 = &g_pool[slot * NG * DD + g0 * DD + c4 * 4];
        atomicMax(p0 + 0, f2key(m0.x));
        atomicMax(p0 + 1, f2key(m0.y));
        atomicMax(p0 + 2, f2key(m0.z));
        atomicMax(p0 + 3, f2key(m0.w));
        if (b < rend) {
            unsigned* p1 = &g_pool[slot * NG * DD + (g0 + 1) * DD + c4 * 4];
            atomicMax(p1 + 0, f2key(m1.x));
            atomicMax(p1 + 1, f2key(m1.y));
            atomicMax(p1 + 2, f2key(m1.z));
            atomicMax(p1 + 3, f2key(m1.w));
        }
    }
}

// ---------------- per-graph max pool for the input layer -----------------------
__global__ void pool_kernel(const float* __restrict__ h, int slot) {
    int g = blockIdx.x, part = blockIdx.y, d = threadIdx.x;
    int lo_g = (g * NN + (NG - 1)) / NG;
    int hi_g = ((g + 1) * NN + (NG - 1)) / NG;
    int chunk = (hi_g - lo_g + 7) >> 3;
    int lo = lo_g + part * chunk;
    int hi = min(hi_g, lo + chunk);
    float m = -3.402823466e38f;
    for (int r = lo; r < hi; r++) m = fmaxf(m, __ldg(&h[r * DD + d]));
    if (hi > lo) atomicMax(&g_pool[slot * NG * DD + g * DD + d], f2key(m));
}

// ---------------- heads: (NH x 4) grid, 16 graphs per block (measured-good) -----
__global__ void heads_kernel(const float* __restrict__ lin_W,
                             const float* __restrict__ lin_b,
                             float* __restrict__ out)
{
    extern __shared__ float sm[];
    float* ps = sm;             // 16*96
    float* ws = sm + 16 * DD;   // 96*96
    int l = blockIdx.x, part = blockIdx.y, tid = threadIdx.x;
    int gbase = part * 16;

    for (int i = tid; i < 16 * DD; i += DD) {
        unsigned key = g_pool[l * NG * DD + gbase * DD + i];
        int b = (key & 0x80000000u) ? (int)(key ^ 0x80000000u) : (int)(~key);
        ps[i] = __int_as_float(b);
    }
    for (int i = tid; i < DD * DD; i += DD) ws[i] = lin_W[l * DD * DD + i];
    __syncthreads();

    float bv = lin_b[l * DD + tid];
    for (int gg = 0; gg < 16; gg++) {
        float acc = bv;
        #pragma unroll 4
        for (int k = 0; k < DD; k++) acc = fmaf(ps[gg * DD + k], ws[k * DD + tid], acc);
        out[(gbase + gg) * (DD * NH) + tid * NH + l] = acc;
    }
}

// ---------------- host orchestration -------------------------------------------
extern "C" void kernel_launch(void* const* d_in, const int* in_sizes, int n_in,
                              void* d_out, int out_size)
{
    const float* h_in   = (const float*)d_in[0];
    const float* W1     = (const float*)d_in[1];
    const float* b1     = (const float*)d_in[2];
    const float* bn1g   = (const float*)d_in[3];
    const float* bn1b   = (const float*)d_in[4];
    const float* W2     = (const float*)d_in[5];
    const float* b2     = (const float*)d_in[6];
    const float* bng    = (const float*)d_in[7];
    const float* bnb    = (const float*)d_in[8];
    const float* prelua = (const float*)d_in[9];
    const float* linW   = (const float*)d_in[10];
    const float* linb   = (const float*)d_in[11];
    const int*   src    = (const int*)d_in[12];
    const int*   dst    = (const int*)d_in[13];
    float* out = (float*)d_out;

    void* p;
    cudaGetSymbolAddress(&p, g_h);     float* hbuf = (float*)p;
    cudaGetSymbolAddress(&p, g_agg);   float* zbuf = (float*)p;
    cudaGetSymbolAddress(&p, g_y);     float* ybuf = (float*)p;
    cudaGetSymbolAddress(&p, g_stats); float* stats = (float*)p;

    const int gemm_smem  = (96 * 100 + DD * DD + 2 * DD) * (int)sizeof(float);  // 76032
    const int heads_smem = (16 * DD + DD * DD) * (int)sizeof(float);            // 43008
    cudaFuncSetAttribute(gemm_kernel<0>, cudaFuncAttributeMaxDynamicSharedMemorySize, gemm_smem);
    cudaFuncSetAttribute(gemm_kernel<1>, cudaFuncAttributeMaxDynamicSharedMemorySize, gemm_smem);
    cudaFuncSetAttribute(heads_kernel,   cudaFuncAttributeMaxDynamicSharedMemorySize, heads_smem);

    const int gemm_blocks = (NN + 95) / 96;     // 521
    const int edge_blocks = (NE + 255) / 256;
    const int agg_blocks  = (NN * 32 + 255) / 256;
    const int pp_blocks   = (NN + 63) / 64;     // 782

    init_kernel<<<128, 256>>>();
    csr_count_kernel<<<edge_blocks, 256>>>(dst);
    scanA_kernel<<<SCAN_BLK, 256>>>();
    scanB_kernel<<<1, 256>>>();
    scanC_kernel<<<SCAN_BLK, 256>>>();
    csr_fill_kernel<<<edge_blocks, 256>>>(src, dst);

    pool_kernel<<<dim3(NG, 8), DD>>>(h_in, 0);

    for (int l = 0; l < NL; l++) {
        const float* hcur = (l == 0) ? h_in : hbuf;
        float* st1 = stats + (l * 2 + 0) * 2 * DD;
        float* st2 = stats + (l * 2 + 1) * 2 * DD;

        agg_kernel<<<agg_blocks, 256>>>(
            reinterpret_cast<const float4*>(hcur),
            reinterpret_cast<float4*>(zbuf));

        gemm_kernel<0><<<gemm_blocks, 256, gemm_smem>>>(
            zbuf, W1 + l * DD * DD, b1 + l * DD,
            nullptr, nullptr, nullptr, ybuf, st1);

        gemm_kernel<1><<<gemm_blocks, 256, gemm_smem>>>(
            ybuf, W2 + l * DD * DD, b2 + l * DD,
            st1, bn1g + l * DD, bn1b + l * DD, zbuf, st2);

        prelupool_kernel<<<pp_blocks, 240>>>(
            st2, bng + l * DD, bnb + l * DD, prelua, l + 1);
    }

    heads_kernel<<<dim3(NH, 4), DD, heads_smem>>>(linW, linb, out);
}